// round 1
// baseline (speedup 1.0000x reference)
#include <cuda_runtime.h>
#include <math.h>

#define D 384
#define KK 16
#define TILE 64
#define TPB 512
#define ROW_PAD 388   // 384 + 4 floats padding: kills smem bank aliasing (384 % 32 == 0)

// ---- scratch accumulators (device globals: no allocation allowed) ----
__device__ float g_P[KK * D];   // P = A^T F   (row-major [k][d])
__device__ float g_cs[KK];      // cluster sizes
__device__ float g_m[KK];       // m = A^T degrees = sum_e w_e * a[dst]
__device__ float g_S1;          // sum_e w_e * dot(a[src], a[dst])
__device__ float g_ne;          // number_of_edges = sum_e w_e

// ------------------------------------------------------------------
__global__ void k_zero()
{
    int i = blockIdx.x * blockDim.x + threadIdx.x;
    if (i < KK * D) g_P[i] = 0.0f;
    if (i < KK) { g_cs[i] = 0.0f; g_m[i] = 0.0f; }
    if (i == 0) { g_S1 = 0.0f; g_ne = 0.0f; }
}

// ------------------------------------------------------------------
// Kernel A: per 64-row tile:
//   logits = F W + b  -> softmax -> assignments (written to gmem + smem)
//   accumulate cluster_sizes, and P += A_tile^T F_tile (register accumulators)
extern __shared__ float smem[];

__global__ __launch_bounds__(TPB) void k_assign(
    const float* __restrict__ F, const float* __restrict__ W,
    const float* __restrict__ b, float* __restrict__ a_out, int N)
{
    float* s_f  = smem;                        // TILE * ROW_PAD
    float* s_Wt = s_f + TILE * ROW_PAD;        // KK * ROW_PAD (W transposed: [k][d])
    float* s_a  = s_Wt + KK * ROW_PAD;         // TILE * KK
    float* s_cs = s_a + TILE * KK;             // KK

    const int t = threadIdx.x;

    // stage W transposed
    for (int i = t; i < D * KK; i += TPB) {
        int d = i / KK, k = i % KK;
        s_Wt[k * ROW_PAD + d] = W[i];
    }
    if (t < KK) s_cs[t] = 0.0f;

    const int lane = t & 31;
    const int wrp  = t >> 5;          // 0..15
    const int k    = lane & 15;       // cluster index for GEMM phase
    const int s    = lane >> 4;       // row sub-slot (0/1)
    const float bk = b[k];

    // P-phase ownership: thread owns d = 3*dt + {0,1,2}, k = 4*kq + {0..3}
    const int dt = t & 127;
    const int kq = t >> 7;
    float pacc[12];
    #pragma unroll
    for (int i = 0; i < 12; i++) pacc[i] = 0.0f;

    __syncthreads();

    const int NT = (N + TILE - 1) / TILE;
    for (int tile = blockIdx.x; tile < NT; tile += gridDim.x) {
        const int base   = tile * TILE;
        const int rows_n = min(TILE, N - base);

        // ---- stage feature tile (coalesced float4) ----
        const float4* F4 = (const float4*)(F + (size_t)base * D);
        for (int i = t; i < TILE * (D / 4); i += TPB) {
            int r = i / (D / 4);
            int c = i % (D / 4);
            float4 v = make_float4(0.f, 0.f, 0.f, 0.f);
            if (r < rows_n) v = F4[r * (D / 4) + c];
            *(float4*)(s_f + r * ROW_PAD + c * 4) = v;
        }
        __syncthreads();

        // ---- GEMM phase: warp handles rows 4w+s and 4w+s+2 ----
        const int r0 = wrp * 4 + s;
        const int r1 = r0 + 2;
        float acc0 = bk, acc1 = bk;
        const float4* wrow = (const float4*)(s_Wt + k * ROW_PAD);
        const float4* f0p  = (const float4*)(s_f + r0 * ROW_PAD);
        const float4* f1p  = (const float4*)(s_f + r1 * ROW_PAD);
        #pragma unroll 8
        for (int j = 0; j < D / 4; j++) {
            float4 wv = wrow[j];
            float4 x  = f0p[j];
            float4 y  = f1p[j];
            acc0 += wv.x * x.x + wv.y * x.y + wv.z * x.z + wv.w * x.w;
            acc1 += wv.x * y.x + wv.y * y.y + wv.z * y.z + wv.w * y.w;
        }

        // ---- softmax over 16 clusters (within 16-lane groups) ----
        float a0, a1;
        {
            float mx = acc0;
            #pragma unroll
            for (int o = 1; o < 16; o <<= 1) mx = fmaxf(mx, __shfl_xor_sync(0xffffffffu, mx, o));
            float e = __expf(acc0 - mx);
            float sm = e;
            #pragma unroll
            for (int o = 1; o < 16; o <<= 1) sm += __shfl_xor_sync(0xffffffffu, sm, o);
            a0 = e / sm;
        }
        {
            float mx = acc1;
            #pragma unroll
            for (int o = 1; o < 16; o <<= 1) mx = fmaxf(mx, __shfl_xor_sync(0xffffffffu, mx, o));
            float e = __expf(acc1 - mx);
            float sm = e;
            #pragma unroll
            for (int o = 1; o < 16; o <<= 1) sm += __shfl_xor_sync(0xffffffffu, sm, o);
            a1 = e / sm;
        }

        const bool v0 = (r0 < rows_n);
        const bool v1 = (r1 < rows_n);
        if (v0) { a_out[(size_t)(base + r0) * KK + k] = a0; s_a[r0 * KK + k] = a0; }
        if (v1) { a_out[(size_t)(base + r1) * KK + k] = a1; s_a[r1 * KK + k] = a1; }
        atomicAdd(&s_cs[k], (v0 ? a0 : 0.0f) + (v1 ? a1 : 0.0f));

        __syncthreads();  // s_a visible to all

        // ---- P phase: pacc[c*4+j] += f[i][3dt+c] * a[i][4kq+j] ----
        for (int i = 0; i < rows_n; i++) {
            float4 av = *(const float4*)(s_a + i * KK + kq * 4);
            float f0v = s_f[i * ROW_PAD + 3 * dt + 0];
            float f1v = s_f[i * ROW_PAD + 3 * dt + 1];
            float f2v = s_f[i * ROW_PAD + 3 * dt + 2];
            pacc[0]  += f0v * av.x; pacc[1]  += f0v * av.y; pacc[2]  += f0v * av.z; pacc[3]  += f0v * av.w;
            pacc[4]  += f1v * av.x; pacc[5]  += f1v * av.y; pacc[6]  += f1v * av.z; pacc[7]  += f1v * av.w;
            pacc[8]  += f2v * av.x; pacc[9]  += f2v * av.y; pacc[10] += f2v * av.z; pacc[11] += f2v * av.w;
        }
        __syncthreads();  // before next tile overwrites s_f / s_a
    }

    // ---- flush P (spread-address global atomics) ----
    #pragma unroll
    for (int c = 0; c < 3; c++) {
        #pragma unroll
        for (int j = 0; j < 4; j++) {
            atomicAdd(&g_P[(kq * 4 + j) * D + (3 * dt + c)], pacc[c * 4 + j]);
        }
    }
    if (t < KK) atomicAdd(&g_cs[t], s_cs[t]);
}

// ------------------------------------------------------------------
// Kernel B: edge pass.
//   S1 += w * dot(a[src], a[dst]);  ne += w;  m[k] += w * a[dst][k]
__global__ __launch_bounds__(256) void k_edges(
    const int* __restrict__ es, const int* __restrict__ ed,
    const float* __restrict__ ew, const float* __restrict__ A, int E)
{
    __shared__ float s_m[KK];
    __shared__ float s_s1, s_ne;
    const int t = threadIdx.x;
    if (t < KK) s_m[t] = 0.0f;
    if (t == 0) { s_s1 = 0.0f; s_ne = 0.0f; }
    __syncthreads();

    float lm[16];
    #pragma unroll
    for (int i = 0; i < 16; i++) lm[i] = 0.0f;
    float ls1 = 0.0f, lne = 0.0f;

    const float4* A4 = (const float4*)A;
    for (int i = blockIdx.x * blockDim.x + t; i < E; i += gridDim.x * blockDim.x) {
        int sn = es[i], dn = ed[i];
        float wv = ew[i];
        float4 x0 = A4[(size_t)sn * 4 + 0], x1 = A4[(size_t)sn * 4 + 1];
        float4 x2 = A4[(size_t)sn * 4 + 2], x3 = A4[(size_t)sn * 4 + 3];
        float4 y0 = A4[(size_t)dn * 4 + 0], y1 = A4[(size_t)dn * 4 + 1];
        float4 y2 = A4[(size_t)dn * 4 + 2], y3 = A4[(size_t)dn * 4 + 3];
        float dot = x0.x * y0.x + x0.y * y0.y + x0.z * y0.z + x0.w * y0.w
                  + x1.x * y1.x + x1.y * y1.y + x1.z * y1.z + x1.w * y1.w
                  + x2.x * y2.x + x2.y * y2.y + x2.z * y2.z + x2.w * y2.w
                  + x3.x * y3.x + x3.y * y3.y + x3.z * y3.z + x3.w * y3.w;
        ls1 += wv * dot;
        lne += wv;
        lm[0]  += wv * y0.x; lm[1]  += wv * y0.y; lm[2]  += wv * y0.z; lm[3]  += wv * y0.w;
        lm[4]  += wv * y1.x; lm[5]  += wv * y1.y; lm[6]  += wv * y1.z; lm[7]  += wv * y1.w;
        lm[8]  += wv * y2.x; lm[9]  += wv * y2.y; lm[10] += wv * y2.z; lm[11] += wv * y2.w;
        lm[12] += wv * y3.x; lm[13] += wv * y3.y; lm[14] += wv * y3.z; lm[15] += wv * y3.w;
    }

    // warp reduce (static indexing only)
    #pragma unroll
    for (int o = 16; o > 0; o >>= 1) {
        ls1 += __shfl_xor_sync(0xffffffffu, ls1, o);
        lne += __shfl_xor_sync(0xffffffffu, lne, o);
    }
    const int lane = t & 31;
    float myv = 0.0f;
    #pragma unroll
    for (int kk2 = 0; kk2 < 16; kk2++) {
        float v = lm[kk2];
        #pragma unroll
        for (int o = 16; o > 0; o >>= 1) v += __shfl_xor_sync(0xffffffffu, v, o);
        if (lane == kk2) myv = v;
    }
    if (lane < 16) atomicAdd(&s_m[lane], myv);
    if (lane == 0) { atomicAdd(&s_s1, ls1); atomicAdd(&s_ne, lne); }
    __syncthreads();
    if (t < KK) atomicAdd(&g_m[t], s_m[t]);
    if (t == 0) { atomicAdd(&g_S1, s_s1); atomicAdd(&g_ne, s_ne); }
}

// ------------------------------------------------------------------
// Kernel C: losses + features_pooled = selu(P / cs)
__global__ void k_final(float* __restrict__ out, int N)
{
    const int gi = blockIdx.x * blockDim.x + threadIdx.x;
    if (gi == 0) {
        float ne = g_ne;
        float msum = 0.0f, csq = 0.0f;
        #pragma unroll
        for (int kk2 = 0; kk2 < KK; kk2++) {
            msum += g_m[kk2] * g_m[kk2];
            csq  += g_cs[kk2] * g_cs[kk2];
        }
        float spectral = -(g_S1 - msum / (2.0f * ne)) / (2.0f * ne);
        float collapse = 0.1f * (sqrtf(csq) / (float)N * 4.0f - 1.0f);  // sqrt(K)=4
        size_t off = (size_t)KK * D + (size_t)N * KK;
        out[off]     = spectral;
        out[off + 1] = collapse;
    }
    if (gi < KK * D) {
        int kk2 = gi / D;
        float x = g_P[gi] / g_cs[kk2];
        const float alpha = 1.6732632423543772f;
        const float scale = 1.0507009873554805f;
        out[gi] = (x > 0.0f) ? scale * x : scale * alpha * expm1f(x);
    }
}

// ------------------------------------------------------------------
extern "C" void kernel_launch(void* const* d_in, const int* in_sizes, int n_in,
                              void* d_out, int out_size)
{
    const float* F  = (const float*)d_in[0];
    const int*   es = (const int*)d_in[1];
    const int*   ed = (const int*)d_in[2];
    const float* ew = (const float*)d_in[3];
    const float* W  = (const float*)d_in[4];
    const float* b  = (const float*)d_in[5];
    const int N = in_sizes[0] / D;
    const int E = in_sizes[1];

    float* out   = (float*)d_out;
    float* a_out = out + KK * D;   // assignments live right after features_pooled

    size_t smem_bytes = (size_t)(TILE * ROW_PAD + KK * ROW_PAD + TILE * KK + KK) * sizeof(float);
    cudaFuncSetAttribute(k_assign, cudaFuncAttributeMaxDynamicSharedMemorySize, (int)smem_bytes);

    k_zero<<<13, 512>>>();
    k_assign<<<148, TPB, smem_bytes>>>(F, W, b, a_out, N);
    k_edges<<<1184, 256>>>(es, ed, ew, a_out, E);
    k_final<<<13, 512>>>(out, N);
}

// round 2
// speedup vs baseline: 1.2569x; 1.2569x over previous
#include <cuda_runtime.h>
#include <math.h>

#define D 384
#define KK 16
#define TILE 64
#define TPB 512
#define ROW_PAD 388   // 384 + 4 floats padding; 388*4=1552B is 16B-aligned per row

// ---- scratch accumulators (device globals: no allocation allowed) ----
__device__ float g_P[KK * D];   // P = A^T F   (row-major [k][d])
__device__ float g_cs[KK];      // cluster sizes
__device__ float g_m[KK];       // m = A^T degrees = sum_e w_e * a[dst]
__device__ float g_S1;          // sum_e w_e * dot(a[src], a[dst])
__device__ float g_ne;          // number_of_edges = sum_e w_e

// ------------------------------------------------------------------
__global__ void k_zero()
{
    int i = blockIdx.x * blockDim.x + threadIdx.x;
    if (i < KK * D) g_P[i] = 0.0f;
    if (i < KK) { g_cs[i] = 0.0f; g_m[i] = 0.0f; }
    if (i == 0) { g_S1 = 0.0f; g_ne = 0.0f; }
}

// ------------------------------------------------------------------
// Kernel A: per 64-row tile:
//   logits = F W + b  -> softmax -> assignments (written to gmem + smem)
//   accumulate cluster_sizes, and P += A_tile^T F_tile (register accumulators)
extern __shared__ float smem[];

__global__ __launch_bounds__(TPB) void k_assign(
    const float* __restrict__ F, const float* __restrict__ W,
    const float* __restrict__ b, float* __restrict__ a_out, int N)
{
    float* s_f  = smem;                        // TILE * ROW_PAD
    float* s_Wt = s_f + TILE * ROW_PAD;        // KK * ROW_PAD (W transposed: [k][d])
    float* s_a  = s_Wt + KK * ROW_PAD;         // TILE * KK
    float* s_cs = s_a + TILE * KK;             // KK

    const int t = threadIdx.x;

    // stage W transposed
    for (int i = t; i < D * KK; i += TPB) {
        int d = i / KK, k = i % KK;
        s_Wt[k * ROW_PAD + d] = W[i];
    }
    if (t < KK) s_cs[t] = 0.0f;

    const int lane = t & 31;
    const int wrp  = t >> 5;          // 0..15
    const int k    = lane & 15;       // cluster index for GEMM phase
    const int s    = lane >> 4;       // row sub-slot (0/1)
    const float bk = b[k];

    // P-phase ownership: 384 active threads; thread owns d-quad dq (0..95),
    // k-quad kq (0..3):  pacc[j*4+c] accumulates a[i][kq*4+j]*f[i][dq*4+c]
    const bool p_act = (t < 384);
    const int dq = t % 96;
    const int kq = t / 96;            // 0..3 for active threads
    float pacc[16];
    #pragma unroll
    for (int i = 0; i < 16; i++) pacc[i] = 0.0f;

    __syncthreads();

    const int NT = (N + TILE - 1) / TILE;
    for (int tile = blockIdx.x; tile < NT; tile += gridDim.x) {
        const int base   = tile * TILE;
        const int rows_n = min(TILE, N - base);

        // ---- stage feature tile (coalesced float4, zero-fill tail rows) ----
        const float4* F4 = (const float4*)(F + (size_t)base * D);
        for (int i = t; i < TILE * (D / 4); i += TPB) {
            int r = i / (D / 4);
            int c = i % (D / 4);
            float4 v = make_float4(0.f, 0.f, 0.f, 0.f);
            if (r < rows_n) v = F4[r * (D / 4) + c];
            *(float4*)(s_f + r * ROW_PAD + c * 4) = v;
        }
        __syncthreads();

        // ---- GEMM phase: warp handles rows 4w+s and 4w+s+2 ----
        const int r0 = wrp * 4 + s;
        const int r1 = r0 + 2;
        float acc0 = bk, acc1 = bk;
        const float4* wrow = (const float4*)(s_Wt + k * ROW_PAD);
        const float4* f0p  = (const float4*)(s_f + r0 * ROW_PAD);
        const float4* f1p  = (const float4*)(s_f + r1 * ROW_PAD);
        #pragma unroll 8
        for (int j = 0; j < D / 4; j++) {
            float4 wv = wrow[j];
            float4 x  = f0p[j];
            float4 y  = f1p[j];
            acc0 += wv.x * x.x + wv.y * x.y + wv.z * x.z + wv.w * x.w;
            acc1 += wv.x * y.x + wv.y * y.y + wv.z * y.z + wv.w * y.w;
        }

        // ---- softmax over 16 clusters (within 16-lane groups) ----
        float a0, a1;
        {
            float mx = acc0;
            #pragma unroll
            for (int o = 1; o < 16; o <<= 1) mx = fmaxf(mx, __shfl_xor_sync(0xffffffffu, mx, o));
            float e = __expf(acc0 - mx);
            float sm = e;
            #pragma unroll
            for (int o = 1; o < 16; o <<= 1) sm += __shfl_xor_sync(0xffffffffu, sm, o);
            a0 = e / sm;
        }
        {
            float mx = acc1;
            #pragma unroll
            for (int o = 1; o < 16; o <<= 1) mx = fmaxf(mx, __shfl_xor_sync(0xffffffffu, mx, o));
            float e = __expf(acc1 - mx);
            float sm = e;
            #pragma unroll
            for (int o = 1; o < 16; o <<= 1) sm += __shfl_xor_sync(0xffffffffu, sm, o);
            a1 = e / sm;
        }

        const bool v0 = (r0 < rows_n);
        const bool v1 = (r1 < rows_n);
        if (v0) { a_out[(size_t)(base + r0) * KK + k] = a0; s_a[r0 * KK + k] = a0; }
        if (v1) { a_out[(size_t)(base + r1) * KK + k] = a1; s_a[r1 * KK + k] = a1; }
        atomicAdd(&s_cs[k], (v0 ? a0 : 0.0f) + (v1 ? a1 : 0.0f));

        __syncthreads();  // s_a visible to all

        // ---- P phase: one LDS.128 (f, conflict-free) + one LDS.128 (a, broadcast) per row ----
        if (p_act) {
            const float* fp = s_f + dq * 4;
            const float* ap = s_a + kq * 4;
            for (int i = 0; i < rows_n; i++) {
                float4 fv = *(const float4*)(fp + i * ROW_PAD);
                float4 av = *(const float4*)(ap + i * KK);
                pacc[0]  += av.x * fv.x; pacc[1]  += av.x * fv.y; pacc[2]  += av.x * fv.z; pacc[3]  += av.x * fv.w;
                pacc[4]  += av.y * fv.x; pacc[5]  += av.y * fv.y; pacc[6]  += av.y * fv.z; pacc[7]  += av.y * fv.w;
                pacc[8]  += av.z * fv.x; pacc[9]  += av.z * fv.y; pacc[10] += av.z * fv.z; pacc[11] += av.z * fv.w;
                pacc[12] += av.w * fv.x; pacc[13] += av.w * fv.y; pacc[14] += av.w * fv.z; pacc[15] += av.w * fv.w;
            }
        }
        __syncthreads();  // before next tile overwrites s_f / s_a
    }

    // ---- flush P (spread-address global reductions) ----
    if (p_act) {
        #pragma unroll
        for (int j = 0; j < 4; j++) {
            #pragma unroll
            for (int c = 0; c < 4; c++) {
                atomicAdd(&g_P[(kq * 4 + j) * D + (dq * 4 + c)], pacc[j * 4 + c]);
            }
        }
    }
    if (t < KK) atomicAdd(&g_cs[t], s_cs[t]);
}

// ------------------------------------------------------------------
// Kernel B: edge pass, 4-lane-cooperative gathers.
//   Each 4-lane group handles one edge; lane sub owns 16B of each 64B row.
//   S1 += w * dot(a[src], a[dst]);  ne += w;  m[k] += w * a[dst][k]
__global__ __launch_bounds__(256) void k_edges(
    const int* __restrict__ es, const int* __restrict__ ed,
    const float* __restrict__ ew, const float* __restrict__ A, int E)
{
    __shared__ float s_m[KK];
    __shared__ float s_s1, s_ne;
    const int t = threadIdx.x;
    if (t < KK) s_m[t] = 0.0f;
    if (t == 0) { s_s1 = 0.0f; s_ne = 0.0f; }
    __syncthreads();

    const int lane = t & 31;
    const int sub  = lane & 3;                          // 16B chunk within row
    const int g0   = blockIdx.x * (blockDim.x >> 2) + (t >> 2);
    const int G    = gridDim.x * (blockDim.x >> 2);

    float lm0 = 0.f, lm1 = 0.f, lm2 = 0.f, lm3 = 0.f;   // k = sub*4 + {0..3}
    float ls1 = 0.f, lne = 0.f;

    const float4* A4 = (const float4*)A;
    for (int e = g0; e < E; e += G) {
        int sn = es[e], dn = ed[e];
        float wv = ew[e];
        float4 x = A4[(size_t)sn * 4 + sub];
        float4 y = A4[(size_t)dn * 4 + sub];
        float dot = x.x * y.x + x.y * y.y + x.z * y.z + x.w * y.w;
        dot += __shfl_xor_sync(0xffffffffu, dot, 1);
        dot += __shfl_xor_sync(0xffffffffu, dot, 2);
        if (sub == 0) { ls1 += wv * dot; lne += wv; }
        lm0 += wv * y.x; lm1 += wv * y.y; lm2 += wv * y.z; lm3 += wv * y.w;
    }

    // reduce lm across the 8 groups of the warp (lanes sharing sub)
    #pragma unroll
    for (int o = 4; o <= 16; o <<= 1) {
        lm0 += __shfl_xor_sync(0xffffffffu, lm0, o);
        lm1 += __shfl_xor_sync(0xffffffffu, lm1, o);
        lm2 += __shfl_xor_sync(0xffffffffu, lm2, o);
        lm3 += __shfl_xor_sync(0xffffffffu, lm3, o);
    }
    // full warp reduce for scalars (non-sub0 lanes contribute 0)
    #pragma unroll
    for (int o = 16; o > 0; o >>= 1) {
        ls1 += __shfl_xor_sync(0xffffffffu, ls1, o);
        lne += __shfl_xor_sync(0xffffffffu, lne, o);
    }
    if (lane < 4) {
        atomicAdd(&s_m[lane * 4 + 0], lm0);
        atomicAdd(&s_m[lane * 4 + 1], lm1);
        atomicAdd(&s_m[lane * 4 + 2], lm2);
        atomicAdd(&s_m[lane * 4 + 3], lm3);
    }
    if (lane == 0) { atomicAdd(&s_s1, ls1); atomicAdd(&s_ne, lne); }
    __syncthreads();
    if (t < KK) atomicAdd(&g_m[t], s_m[t]);
    if (t == 0) { atomicAdd(&g_S1, s_s1); atomicAdd(&g_ne, s_ne); }
}

// ------------------------------------------------------------------
// Kernel C: losses + features_pooled = selu(P / cs)
__global__ void k_final(float* __restrict__ out, int N)
{
    const int gi = blockIdx.x * blockDim.x + threadIdx.x;
    if (gi == 0) {
        float ne = g_ne;
        float msum = 0.0f, csq = 0.0f;
        #pragma unroll
        for (int kk2 = 0; kk2 < KK; kk2++) {
            msum += g_m[kk2] * g_m[kk2];
            csq  += g_cs[kk2] * g_cs[kk2];
        }
        float spectral = -(g_S1 - msum / (2.0f * ne)) / (2.0f * ne);
        float collapse = 0.1f * (sqrtf(csq) / (float)N * 4.0f - 1.0f);  // sqrt(K)=4
        size_t off = (size_t)KK * D + (size_t)N * KK;
        out[off]     = spectral;
        out[off + 1] = collapse;
    }
    if (gi < KK * D) {
        int kk2 = gi / D;
        float x = g_P[gi] / g_cs[kk2];
        const float alpha = 1.6732632423543772f;
        const float scale = 1.0507009873554805f;
        out[gi] = (x > 0.0f) ? scale * x : scale * alpha * expm1f(x);
    }
}

// ------------------------------------------------------------------
extern "C" void kernel_launch(void* const* d_in, const int* in_sizes, int n_in,
                              void* d_out, int out_size)
{
    const float* F  = (const float*)d_in[0];
    const int*   es = (const int*)d_in[1];
    const int*   ed = (const int*)d_in[2];
    const float* ew = (const float*)d_in[3];
    const float* W  = (const float*)d_in[4];
    const float* b  = (const float*)d_in[5];
    const int N = in_sizes[0] / D;
    const int E = in_sizes[1];

    float* out   = (float*)d_out;
    float* a_out = out + KK * D;   // assignments live right after features_pooled

    size_t smem_bytes = (size_t)(TILE * ROW_PAD + KK * ROW_PAD + TILE * KK + KK) * sizeof(float);
    cudaFuncSetAttribute(k_assign, cudaFuncAttributeMaxDynamicSharedMemorySize, (int)smem_bytes);

    k_zero<<<13, 512>>>();
    k_assign<<<148, TPB, smem_bytes>>>(F, W, b, a_out, N);
    k_edges<<<1184, 256>>>(es, ed, ew, a_out, E);
    k_final<<<13, 512>>>(out, N);
}

// round 3
// speedup vs baseline: 1.3297x; 1.0579x over previous
#include <cuda_runtime.h>
#include <cuda_bf16.h>
#include <math.h>

#define D 384
#define KK 16
#define TILE 64
#define TPB 512
#define ROW_PAD 388   // 384 + 4 floats padding; row stride 1552B (16B aligned)
#define NMAX 100000

// ---- scratch accumulators (device globals: no allocation allowed) ----
__device__ float g_P[KK * D];   // P = A^T F   (row-major [k][d])
__device__ float g_cs[KK];      // cluster sizes
__device__ float g_m[KK];       // m = A^T degrees = sum_e w_e * a[dst]
__device__ float g_S1;          // sum_e w_e * dot(a[src], a[dst])
__device__ float g_ne;          // number_of_edges = sum_e w_e
__device__ __nv_bfloat16 g_A16[NMAX * KK];   // bf16 assignment table (3.2MB, L2-resident)

// ------------------------------------------------------------------
__global__ void k_zero()
{
    int i = blockIdx.x * blockDim.x + threadIdx.x;
    if (i < KK * D) g_P[i] = 0.0f;
    if (i < KK) { g_cs[i] = 0.0f; g_m[i] = 0.0f; }
    if (i == 0) { g_S1 = 0.0f; g_ne = 0.0f; }
}

// ------------------------------------------------------------------
// Kernel A: per 64-row tile:
//   logits = F W + b -> softmax -> assignments (fp32 out + bf16 table + smem)
//   cluster_sizes accumulated in registers; P += A_tile^T F_tile in registers.
extern __shared__ float smem[];

__global__ __launch_bounds__(TPB) void k_assign(
    const float* __restrict__ F, const float* __restrict__ W,
    const float* __restrict__ b, float* __restrict__ a_out, int N)
{
    float* s_f  = smem;                        // TILE * ROW_PAD
    float* s_Wt = s_f + TILE * ROW_PAD;        // KK * ROW_PAD (W transposed: [k][d])
    float* s_a  = s_Wt + KK * ROW_PAD;         // TILE * KK
    float* s_cs = s_a + TILE * KK;             // KK (end-of-kernel flush only)

    const int t = threadIdx.x;

    // stage W transposed
    for (int i = t; i < D * KK; i += TPB) {
        int d = i / KK, k = i % KK;
        s_Wt[k * ROW_PAD + d] = W[i];
    }
    if (t < KK) s_cs[t] = 0.0f;

    const int lane = t & 31;
    const int wrp  = t >> 5;          // 0..15
    const int k    = lane & 15;       // cluster index for GEMM phase
    const int s    = lane >> 4;       // row sub-slot (0/1)
    const float bk = b[k];
    float csacc = 0.0f;               // running cluster-size partial for cluster k

    // P-phase ownership: 384 active threads; thread owns d-quad dq (0..95),
    // k-quad kq (0..3):  pacc[j*4+c] accumulates a[i][kq*4+j]*f[i][dq*4+c]
    const bool p_act = (t < 384);
    const int dq = t % 96;
    const int kq = t / 96;
    float pacc[16];
    #pragma unroll
    for (int i = 0; i < 16; i++) pacc[i] = 0.0f;

    __syncthreads();

    const int NT = (N + TILE - 1) / TILE;
    for (int tile = blockIdx.x; tile < NT; tile += gridDim.x) {
        const int base   = tile * TILE;
        const int rows_n = min(TILE, N - base);

        // ---- stage feature tile (coalesced float4, zero-fill tail rows) ----
        const float4* F4 = (const float4*)(F + (size_t)base * D);
        for (int i = t; i < TILE * (D / 4); i += TPB) {
            int r = i / (D / 4);
            int c = i % (D / 4);
            float4 v = make_float4(0.f, 0.f, 0.f, 0.f);
            if (r < rows_n) v = F4[r * (D / 4) + c];
            *(float4*)(s_f + r * ROW_PAD + c * 4) = v;
        }
        __syncthreads();

        // ---- GEMM phase: warp handles rows 4w+s and 4w+s+2 ----
        const int r0 = wrp * 4 + s;
        const int r1 = r0 + 2;
        float acc0 = bk, acc1 = bk;
        const float4* wrow = (const float4*)(s_Wt + k * ROW_PAD);
        const float4* f0p  = (const float4*)(s_f + r0 * ROW_PAD);
        const float4* f1p  = (const float4*)(s_f + r1 * ROW_PAD);
        #pragma unroll 8
        for (int j = 0; j < D / 4; j++) {
            float4 wv = wrow[j];
            float4 x  = f0p[j];
            float4 y  = f1p[j];
            acc0 += wv.x * x.x + wv.y * x.y + wv.z * x.z + wv.w * x.w;
            acc1 += wv.x * y.x + wv.y * y.y + wv.z * y.z + wv.w * y.w;
        }

        // ---- softmax over 16 clusters (within 16-lane groups) ----
        float a0, a1;
        {
            float mx = acc0;
            #pragma unroll
            for (int o = 1; o < 16; o <<= 1) mx = fmaxf(mx, __shfl_xor_sync(0xffffffffu, mx, o));
            float e = __expf(acc0 - mx);
            float sm = e;
            #pragma unroll
            for (int o = 1; o < 16; o <<= 1) sm += __shfl_xor_sync(0xffffffffu, sm, o);
            a0 = e / sm;
        }
        {
            float mx = acc1;
            #pragma unroll
            for (int o = 1; o < 16; o <<= 1) mx = fmaxf(mx, __shfl_xor_sync(0xffffffffu, mx, o));
            float e = __expf(acc1 - mx);
            float sm = e;
            #pragma unroll
            for (int o = 1; o < 16; o <<= 1) sm += __shfl_xor_sync(0xffffffffu, sm, o);
            a1 = e / sm;
        }

        const bool v0 = (r0 < rows_n);
        const bool v1 = (r1 < rows_n);
        if (v0) {
            a_out[(size_t)(base + r0) * KK + k] = a0;
            g_A16[(size_t)(base + r0) * KK + k] = __float2bfloat16_rn(a0);
            s_a[r0 * KK + k] = a0;
            csacc += a0;
        }
        if (v1) {
            a_out[(size_t)(base + r1) * KK + k] = a1;
            g_A16[(size_t)(base + r1) * KK + k] = __float2bfloat16_rn(a1);
            s_a[r1 * KK + k] = a1;
            csacc += a1;
        }

        __syncthreads();  // s_a visible to all

        // ---- P phase: one LDS.128 (f, conflict-free) + one LDS.128 (a, broadcast) per row ----
        if (p_act) {
            const float* fp = s_f + dq * 4;
            const float* ap = s_a + kq * 4;
            for (int i = 0; i < rows_n; i++) {
                float4 fv = *(const float4*)(fp + i * ROW_PAD);
                float4 av = *(const float4*)(ap + i * KK);
                pacc[0]  += av.x * fv.x; pacc[1]  += av.x * fv.y; pacc[2]  += av.x * fv.z; pacc[3]  += av.x * fv.w;
                pacc[4]  += av.y * fv.x; pacc[5]  += av.y * fv.y; pacc[6]  += av.y * fv.z; pacc[7]  += av.y * fv.w;
                pacc[8]  += av.z * fv.x; pacc[9]  += av.z * fv.y; pacc[10] += av.z * fv.z; pacc[11] += av.z * fv.w;
                pacc[12] += av.w * fv.x; pacc[13] += av.w * fv.y; pacc[14] += av.w * fv.z; pacc[15] += av.w * fv.w;
            }
        }
        __syncthreads();  // before next tile overwrites s_f / s_a
    }

    // ---- flush cluster sizes: fold s=1 half onto s=0, then one smem atomic per lane<16 ----
    csacc += __shfl_xor_sync(0xffffffffu, csacc, 16);
    if (lane < 16) atomicAdd(&s_cs[k], csacc);

    // ---- flush P (spread-address global reductions, once per kernel) ----
    if (p_act) {
        #pragma unroll
        for (int j = 0; j < 4; j++) {
            #pragma unroll
            for (int c = 0; c < 4; c++) {
                atomicAdd(&g_P[(kq * 4 + j) * D + (dq * 4 + c)], pacc[j * 4 + c]);
            }
        }
    }
    __syncthreads();
    if (t < KK) atomicAdd(&g_cs[t], s_cs[t]);
}

// ------------------------------------------------------------------
// Kernel B: edge pass over bf16 assignment table (32B rows).
//   4-lane group per edge; lane sub owns 8B (4 bf16) of each row.
//   S1 += w * dot(a[src], a[dst]);  ne += w;  m[k] += w * a[dst][k]
__global__ __launch_bounds__(256) void k_edges(
    const int* __restrict__ es, const int* __restrict__ ed,
    const float* __restrict__ ew, int E)
{
    __shared__ float s_m[KK];
    __shared__ float s_s1, s_ne;
    const int t = threadIdx.x;
    if (t < KK) s_m[t] = 0.0f;
    if (t == 0) { s_s1 = 0.0f; s_ne = 0.0f; }
    __syncthreads();

    const int lane = t & 31;
    const int sub  = lane & 3;                          // 8B chunk within 32B row
    const int g0   = blockIdx.x * (blockDim.x >> 2) + (t >> 2);
    const int G    = gridDim.x * (blockDim.x >> 2);

    float lm0 = 0.f, lm1 = 0.f, lm2 = 0.f, lm3 = 0.f;   // k = sub*4 + {0..3}
    float ls1 = 0.f, lne = 0.f;

    const uint2* A2 = (const uint2*)g_A16;              // 4 uint2 per row
    for (int e = g0; e < E; e += G) {
        int sn = es[e], dn = ed[e];
        float wv = ew[e];
        uint2 xb = A2[(size_t)sn * 4 + sub];
        uint2 yb = A2[(size_t)dn * 4 + sub];
        float2 x0 = __bfloat1622float2(*(const __nv_bfloat162*)&xb.x);
        float2 x1 = __bfloat1622float2(*(const __nv_bfloat162*)&xb.y);
        float2 y0 = __bfloat1622float2(*(const __nv_bfloat162*)&yb.x);
        float2 y1 = __bfloat1622float2(*(const __nv_bfloat162*)&yb.y);
        float dot = x0.x * y0.x + x0.y * y0.y + x1.x * y1.x + x1.y * y1.y;
        dot += __shfl_xor_sync(0xffffffffu, dot, 1);
        dot += __shfl_xor_sync(0xffffffffu, dot, 2);
        if (sub == 0) { ls1 += wv * dot; lne += wv; }
        lm0 += wv * y0.x; lm1 += wv * y0.y; lm2 += wv * y1.x; lm3 += wv * y1.y;
    }

    // reduce lm across the 8 groups of the warp (lanes sharing sub)
    #pragma unroll
    for (int o = 4; o <= 16; o <<= 1) {
        lm0 += __shfl_xor_sync(0xffffffffu, lm0, o);
        lm1 += __shfl_xor_sync(0xffffffffu, lm1, o);
        lm2 += __shfl_xor_sync(0xffffffffu, lm2, o);
        lm3 += __shfl_xor_sync(0xffffffffu, lm3, o);
    }
    // full warp reduce for scalars (non-sub0 lanes contribute 0)
    #pragma unroll
    for (int o = 16; o > 0; o >>= 1) {
        ls1 += __shfl_xor_sync(0xffffffffu, ls1, o);
        lne += __shfl_xor_sync(0xffffffffu, lne, o);
    }
    if (lane < 4) {
        atomicAdd(&s_m[lane * 4 + 0], lm0);
        atomicAdd(&s_m[lane * 4 + 1], lm1);
        atomicAdd(&s_m[lane * 4 + 2], lm2);
        atomicAdd(&s_m[lane * 4 + 3], lm3);
    }
    if (lane == 0) { atomicAdd(&s_s1, ls1); atomicAdd(&s_ne, lne); }
    __syncthreads();
    if (t < KK) atomicAdd(&g_m[t], s_m[t]);
    if (t == 0) { atomicAdd(&g_S1, s_s1); atomicAdd(&g_ne, s_ne); }
}

// ------------------------------------------------------------------
// Kernel C: losses + features_pooled = selu(P / cs)
__global__ void k_final(float* __restrict__ out, int N)
{
    const int gi = blockIdx.x * blockDim.x + threadIdx.x;
    if (gi == 0) {
        float ne = g_ne;
        float msum = 0.0f, csq = 0.0f;
        #pragma unroll
        for (int kk2 = 0; kk2 < KK; kk2++) {
            msum += g_m[kk2] * g_m[kk2];
            csq  += g_cs[kk2] * g_cs[kk2];
        }
        float spectral = -(g_S1 - msum / (2.0f * ne)) / (2.0f * ne);
        float collapse = 0.1f * (sqrtf(csq) / (float)N * 4.0f - 1.0f);  // sqrt(K)=4
        size_t off = (size_t)KK * D + (size_t)N * KK;
        out[off]     = spectral;
        out[off + 1] = collapse;
    }
    if (gi < KK * D) {
        int kk2 = gi / D;
        float x = g_P[gi] / g_cs[kk2];
        const float alpha = 1.6732632423543772f;
        const float scale = 1.0507009873554805f;
        out[gi] = (x > 0.0f) ? scale * x : scale * alpha * expm1f(x);
    }
}

// ------------------------------------------------------------------
extern "C" void kernel_launch(void* const* d_in, const int* in_sizes, int n_in,
                              void* d_out, int out_size)
{
    const float* F  = (const float*)d_in[0];
    const int*   es = (const int*)d_in[1];
    const int*   ed = (const int*)d_in[2];
    const float* ew = (const float*)d_in[3];
    const float* W  = (const float*)d_in[4];
    const float* b  = (const float*)d_in[5];
    const int N = in_sizes[0] / D;
    const int E = in_sizes[1];

    float* out   = (float*)d_out;
    float* a_out = out + KK * D;   // assignments live right after features_pooled

    size_t smem_bytes = (size_t)(TILE * ROW_PAD + KK * ROW_PAD + TILE * KK + KK) * sizeof(float);
    cudaFuncSetAttribute(k_assign, cudaFuncAttributeMaxDynamicSharedMemorySize, (int)smem_bytes);

    k_zero<<<13, 512>>>();
    k_assign<<<148, TPB, smem_bytes>>>(F, W, b, a_out, N);
    k_edges<<<1184, 256>>>(es, ed, ew, E);
    k_final<<<13, 512>>>(out, N);
}